// round 10
// baseline (speedup 1.0000x reference)
#include <cuda_runtime.h>
#include <cuda_bf16.h>
#include <math.h>
#include <stdint.h>

// Problem constants
#define BB    4
#define NN    4096
#define DD    256
#define MM    (BB * NN)        // 16384 flattened rows
#define MAXNZ 128

// ---------------------------------------------------------------------------
// Scratch (static __device__ — no allocations allowed)
// ---------------------------------------------------------------------------
static __device__ float          g_norm[MM];
static __device__ int            g_nnz[MM];
static __device__ int            g_cidx[MM * MAXNZ];
static __device__ float          g_cval[MM * MAXNZ];
static __device__ float          g_h[MM * DD];      // raw x@theta (no norm)
static __device__ float          g_het[MM * DD];    // x@W_h
static __device__ float          g_gate[MM * DD];   // sigmoid(x@W_t + b_t)
static __device__ __nv_bfloat16  g_xhi[MM * DD];
static __device__ __nv_bfloat16  g_xlo[MM * DD];
// W^T splits: [mat][hi/lo][n][k], each DD*DD
static __device__ __nv_bfloat16  g_wt[3 * 2 * DD * DD];

// ---------------------------------------------------------------------------
// PTX helpers (plain sm_100 target: mma.sync / ldmatrix / cp.async)
// ---------------------------------------------------------------------------
__device__ __forceinline__ uint32_t smem_u32(const void* p) {
    uint32_t a;
    asm("{ .reg .u64 t; cvta.to.shared.u64 t, %1; cvt.u32.u64 %0, t; }" : "=r"(a) : "l"(p));
    return a;
}
__device__ __forceinline__ void cp16(uint32_t dst, const void* src) {
    asm volatile("cp.async.cg.shared.global [%0], [%1], 16;" :: "r"(dst), "l"(src));
}
#define CP_COMMIT() asm volatile("cp.async.commit_group;" ::: "memory")
#define CP_WAIT(n)  asm volatile("cp.async.wait_group %0;" :: "n"(n) : "memory")

__device__ __forceinline__ void ldsm4(uint32_t* r, uint32_t a) {
    asm volatile("ldmatrix.sync.aligned.m8n8.x4.shared.b16 {%0,%1,%2,%3}, [%4];"
        : "=r"(r[0]), "=r"(r[1]), "=r"(r[2]), "=r"(r[3]) : "r"(a));
}
__device__ __forceinline__ void mma16816(float* d, const uint32_t* a, const uint32_t* b) {
    asm volatile(
        "mma.sync.aligned.m16n8k16.row.col.f32.bf16.bf16.f32 "
        "{%0,%1,%2,%3}, {%4,%5,%6,%7}, {%8,%9}, {%0,%1,%2,%3};"
        : "+f"(d[0]), "+f"(d[1]), "+f"(d[2]), "+f"(d[3])
        : "r"(a[0]), "r"(a[1]), "r"(a[2]), "r"(a[3]), "r"(b[0]), "r"(b[1]));
}

// SW128 swizzle for 128B rows: bank-rotate 16B chunks by row within 8-row group
__device__ __forceinline__ int swz128(int row, int intra) {
    return row * 128 + (intra ^ ((row & 7) * 16));
}

// ---------------------------------------------------------------------------
// K0a: split x into bf16 hi/lo
// ---------------------------------------------------------------------------
__global__ __launch_bounds__(256) void k_split_x(const float* __restrict__ x) {
    int i = blockIdx.x * blockDim.x + threadIdx.x;   // over MM*DD/4
    float4 v = ((const float4*)x)[i];
    __nv_bfloat16 hx = __float2bfloat16(v.x), hy = __float2bfloat16(v.y);
    __nv_bfloat16 hz = __float2bfloat16(v.z), hw = __float2bfloat16(v.w);
    __nv_bfloat16 lx = __float2bfloat16(v.x - __bfloat162float(hx));
    __nv_bfloat16 ly = __float2bfloat16(v.y - __bfloat162float(hy));
    __nv_bfloat16 lz = __float2bfloat16(v.z - __bfloat162float(hz));
    __nv_bfloat16 lw = __float2bfloat16(v.w - __bfloat162float(hw));
    __nv_bfloat162* ph = (__nv_bfloat162*)&g_xhi[i * 4];
    __nv_bfloat162* pl = (__nv_bfloat162*)&g_xlo[i * 4];
    ph[0] = __nv_bfloat162(hx, hy); ph[1] = __nv_bfloat162(hz, hw);
    pl[0] = __nv_bfloat162(lx, ly); pl[1] = __nv_bfloat162(lz, lw);
}

// ---------------------------------------------------------------------------
// K0b: build W^T hi/lo for the 3 weight matrices
// ---------------------------------------------------------------------------
__global__ __launch_bounds__(256) void k_prep_w(const float* __restrict__ theta,
                                                const float* __restrict__ Wh,
                                                const float* __restrict__ Wt) {
    int i = blockIdx.x * blockDim.x + threadIdx.x;   // over 3*DD*DD
    int mat = i >> 16;
    int r   = i & 65535;
    int n   = r >> 8;
    int k   = r & 255;
    const float* W = (mat == 0) ? theta : (mat == 1) ? Wh : Wt;
    float v = W[k * DD + n];
    __nv_bfloat16 hi = __float2bfloat16(v);
    __nv_bfloat16 lo = __float2bfloat16(v - __bfloat162float(hi));
    g_wt[((size_t)(mat * 2 + 0) << 16) + n * DD + k] = hi;
    g_wt[((size_t)(mat * 2 + 1) << 16) + n * DD + k] = lo;
}

// ---------------------------------------------------------------------------
// K1: CSR extraction, ballot+popc compaction (no shfl-scan chain).
// 4 rows per warp, batches of 8 float4 loads in flight. HBM-bound.
// Order within a row is component-major per 128-col group — order-independent.
// ---------------------------------------------------------------------------
__global__ __launch_bounds__(256) void k_deg_csr(const float* __restrict__ adj) {
    const int wid  = threadIdx.x >> 5;
    const int lane = threadIdx.x & 31;
    const unsigned lt = (1u << lane) - 1u;
    const int wbase = (blockIdx.x * 8 + wid) * 4;
    for (int rr = 0; rr < 4; ++rr) {
        const int w = wbase + rr;
        const float4* rowp = (const float4*)(adj + (size_t)w * NN);
        const int base_out = w * MAXNZ;
        const int bbase    = w & ~(NN - 1);
        float degacc = 0.f;
        int   cnt    = 0;
        for (int it4 = 0; it4 < 4; ++it4) {
            float4 v[8];
            #pragma unroll
            for (int j = 0; j < 8; ++j)
                v[j] = rowp[it4 * 256 + j * 32 + lane];
            #pragma unroll
            for (int j = 0; j < 8; ++j) {
                degacc += fabsf(v[j].x) + fabsf(v[j].y) + fabsf(v[j].z) + fabsf(v[j].w);
                unsigned bx = __ballot_sync(0xffffffffu, v[j].x != 0.f);
                unsigned by = __ballot_sync(0xffffffffu, v[j].y != 0.f);
                unsigned bz = __ballot_sync(0xffffffffu, v[j].z != 0.f);
                unsigned bw = __ballot_sync(0xffffffffu, v[j].w != 0.f);
                int cx = __popc(bx), cy = __popc(by), cz = __popc(bz), cw = __popc(bw);
                int col = bbase + (it4 * 8 + j) * 128 + lane * 4;
                int px = cnt + __popc(bx & lt);
                int py = cnt + cx + __popc(by & lt);
                int pz = cnt + cx + cy + __popc(bz & lt);
                int pw = cnt + cx + cy + cz + __popc(bw & lt);
                if (v[j].x != 0.f && px < MAXNZ) { g_cidx[base_out + px] = col + 0; g_cval[base_out + px] = v[j].x; }
                if (v[j].y != 0.f && py < MAXNZ) { g_cidx[base_out + py] = col + 1; g_cval[base_out + py] = v[j].y; }
                if (v[j].z != 0.f && pz < MAXNZ) { g_cidx[base_out + pz] = col + 2; g_cval[base_out + pz] = v[j].z; }
                if (v[j].w != 0.f && pw < MAXNZ) { g_cidx[base_out + pw] = col + 3; g_cval[base_out + pw] = v[j].w; }
                cnt += cx + cy + cz + cw;
            }
        }
        #pragma unroll
        for (int o = 16; o; o >>= 1)
            degacc += __shfl_xor_sync(0xffffffffu, degacc, o);
        if (lane == 0) {
            g_nnz[w]  = cnt < MAXNZ ? cnt : MAXNZ;
            g_norm[w] = rsqrtf(degacc + 1e-6f);
        }
    }
}

// ---------------------------------------------------------------------------
// K2: bf16-split GEMM via mma.sync.m16n8k16.
// CTA tile 128x128 (8 warps: 4m x 2n). BK=64, 3-stage cp.async ring (96KB
// dynamic smem), one __syncthreads per iteration.
// B fragments double-buffered across ks (load ks+1 while mma ks); swizzled
// ldsm addresses computed inline from row base/xor regs to stay under 128 regs.
// ---------------------------------------------------------------------------
#define TILE_B   (128 * 128)         // 16384 bytes per tile (A or B)
#define STAGE_B  (2 * TILE_B)        // 32768
#define GEMM_SMEM (3 * STAGE_B)      // 98304

__global__ __launch_bounds__(256, 2) void k_gemm_mma(const float* __restrict__ bt) {
    extern __shared__ __align__(128) char sm[];

    const int tid  = threadIdx.x;
    const int wid  = tid >> 5;
    const int lane = tid & 31;
    const int wm   = wid & 3;
    const int wn   = wid >> 2;
    const int g    = lane >> 3;
    const int lr   = lane & 7;

    const int mat   = blockIdx.y >> 1;
    const int nhalf = blockIdx.y & 1;
    const int m0    = blockIdx.x * 128;
    const int n0    = nhalf * 128;
    const __nv_bfloat16* wt_hi = g_wt + ((size_t)(mat * 2) << 16);
    const __nv_bfloat16* wt_lo = wt_hi + (1 << 16);

    const uint32_t smb = smem_u32(sm);

    float acc[2][8][4] = {};

    // One stage = full 64-wide K slab of A and B (each 128 rows x 128B).
    auto load_stage = [&](int iter, int stage) {
        const int seg = iter >> 2;              // 12 iters -> 3 segs of 4
        const int k0  = (iter & 3) * 64;
        const __nv_bfloat16* Asrc = (seg < 2) ? g_xhi : g_xlo;
        const __nv_bfloat16* Bsrc = (seg == 1) ? wt_lo : wt_hi;
        const uint32_t sa = smb + stage * STAGE_B;
        const uint32_t sb = sa + TILE_B;
        #pragma unroll
        for (int j = 0; j < 4; ++j) {
            int id  = tid + j * 256;            // 0..1023
            int row = id >> 3, c = id & 7;
            int so  = swz128(row, c * 16);
            cp16(sa + so, Asrc + (size_t)(m0 + row) * DD + k0 + c * 8);
            cp16(sb + so, Bsrc + (size_t)(n0 + row) * DD + k0 + c * 8);
        }
        CP_COMMIT();
    };

    // Row base / swizzle-xor regs; addresses built inline per ldsm.
    const int ah = (g >> 1) * 16;    // A intra-row half offset
    const int bh = (g & 1) * 16;     // B intra-row half offset
    int arow[2], axr[2], brow[4], bxr[4];
    #pragma unroll
    for (int mi = 0; mi < 2; ++mi) {
        int r = wm * 32 + mi * 16 + (g & 1) * 8 + lr;
        arow[mi] = r * 128;
        axr[mi]  = (r & 7) * 16;
    }
    #pragma unroll
    for (int nt = 0; nt < 4; ++nt) {
        int r = wn * 64 + nt * 16 + (g >> 1) * 8 + lr;
        brow[nt] = r * 128;
        bxr[nt]  = (r & 7) * 16;
    }

    load_stage(0, 0);
    load_stage(1, 1);

    int stage = 0;
    for (int it = 0; it < 12; ++it) {
        CP_WAIT(1);
        __syncthreads();

        if (it + 2 < 12) load_stage(it + 2, (stage + 2) % 3);

        const uint32_t sa = smb + stage * STAGE_B;
        const uint32_t sb = sa + TILE_B;

        // B-fragment double buffer: load ks=0, then per ks prefetch ks+1.
        uint32_t bf[2][4][4];
        #pragma unroll
        for (int nt = 0; nt < 4; ++nt)
            ldsm4(bf[0][nt], sb + brow[nt] + ((0 * 32 + bh) ^ bxr[nt]));

        #pragma unroll
        for (int ks = 0; ks < 4; ++ks) {
            const int cur = ks & 1;
            uint32_t af[2][4];
            #pragma unroll
            for (int mi = 0; mi < 2; ++mi)
                ldsm4(af[mi], sa + arow[mi] + ((ks * 32 + ah) ^ axr[mi]));
            if (ks < 3) {
                #pragma unroll
                for (int nt = 0; nt < 4; ++nt)
                    ldsm4(bf[cur ^ 1][nt], sb + brow[nt] + (((ks + 1) * 32 + bh) ^ bxr[nt]));
            }
            #pragma unroll
            for (int mi = 0; mi < 2; ++mi)
                #pragma unroll
                for (int ni = 0; ni < 8; ++ni)
                    mma16816(acc[mi][ni], af[mi], &bf[cur][ni >> 1][(ni & 1) * 2]);
        }
        stage = (stage + 1) % 3;
    }

    float* dst = (mat == 0) ? g_h : (mat == 1) ? g_het : g_gate;
    #pragma unroll
    for (int mi = 0; mi < 2; ++mi) {
        #pragma unroll
        for (int rh = 0; rh < 2; ++rh) {
            const int r = m0 + wm * 32 + mi * 16 + rh * 8 + (lane >> 2);
            #pragma unroll
            for (int ni = 0; ni < 8; ++ni) {
                const int c = n0 + wn * 64 + ni * 8 + (lane & 3) * 2;
                float v0 = acc[mi][ni][rh * 2];
                float v1 = acc[mi][ni][rh * 2 + 1];
                if (mat == 2) {
                    v0 = 1.f / (1.f + expf(-(v0 + bt[c])));
                    v1 = 1.f / (1.f + expf(-(v1 + bt[c + 1])));
                }
                *(float2*)(dst + (size_t)r * DD + c) = make_float2(v0, v1);
            }
        }
    }
}

// ---------------------------------------------------------------------------
// K3: vectorized sparse gather + gate/combine + ELU.
// 4 rows per block, 64 threads per row, float4 per thread.
// ---------------------------------------------------------------------------
__global__ __launch_bounds__(256) void k_spmm(float* __restrict__ out) {
    const int grp = threadIdx.x >> 6;     // row within block (0..3)
    const int ch  = threadIdx.x & 63;     // channel group (x4)
    const int row = blockIdx.x * 4 + grp;

    __shared__ int   soff[4][MAXNZ];
    __shared__ float sval[4][MAXNZ];

    const int nnz = g_nnz[row];
    #pragma unroll
    for (int j = 0; j < 2; ++j) {
        int e = ch + j * 64;
        if (e < nnz) {
            int o = row * MAXNZ + e;
            int s = g_cidx[o];
            soff[grp][e] = s * DD;
            sval[grp][e] = g_cval[o] * g_norm[s];
        }
    }
    __syncthreads();

    const float* hbase = g_h + ch * 4;
    float4 acc = make_float4(0.f, 0.f, 0.f, 0.f);
    int e = 0;
    #pragma unroll 1
    for (; e + 4 <= nnz; e += 4) {
        float4 h0 = *(const float4*)(hbase + soff[grp][e]);
        float4 h1 = *(const float4*)(hbase + soff[grp][e + 1]);
        float4 h2 = *(const float4*)(hbase + soff[grp][e + 2]);
        float4 h3 = *(const float4*)(hbase + soff[grp][e + 3]);
        float v0 = sval[grp][e],     v1 = sval[grp][e + 1];
        float v2 = sval[grp][e + 2], v3 = sval[grp][e + 3];
        acc.x += v0 * h0.x; acc.y += v0 * h0.y; acc.z += v0 * h0.z; acc.w += v0 * h0.w;
        acc.x += v1 * h1.x; acc.y += v1 * h1.y; acc.z += v1 * h1.z; acc.w += v1 * h1.w;
        acc.x += v2 * h2.x; acc.y += v2 * h2.y; acc.z += v2 * h2.z; acc.w += v2 * h2.w;
        acc.x += v3 * h3.x; acc.y += v3 * h3.y; acc.z += v3 * h3.z; acc.w += v3 * h3.w;
    }
    for (; e < nnz; ++e) {
        float v = sval[grp][e];
        float4 hv = *(const float4*)(hbase + soff[grp][e]);
        acc.x += v * hv.x; acc.y += v * hv.y; acc.z += v * hv.z; acc.w += v * hv.w;
    }

    const size_t o = (size_t)row * DD + ch * 4;
    const float nrm = g_norm[row];
    float4 gt = *(const float4*)(g_gate + o);
    float4 ht = *(const float4*)(g_het + o);
    float4 f;
    f.x = gt.x * (acc.x * nrm) + (1.f - gt.x) * ht.x;
    f.y = gt.y * (acc.y * nrm) + (1.f - gt.y) * ht.y;
    f.z = gt.z * (acc.z * nrm) + (1.f - gt.z) * ht.z;
    f.w = gt.w * (acc.w * nrm) + (1.f - gt.w) * ht.w;
    f.x = f.x > 0.f ? f.x : expm1f(f.x);
    f.y = f.y > 0.f ? f.y : expm1f(f.y);
    f.z = f.z > 0.f ? f.z : expm1f(f.z);
    f.w = f.w > 0.f ? f.w : expm1f(f.w);
    *(float4*)(out + o) = f;
}

// ---------------------------------------------------------------------------
extern "C" void kernel_launch(void* const* d_in, const int* in_sizes, int n_in,
                              void* d_out, int out_size) {
    const float* x     = (const float*)d_in[0];
    const float* adj   = (const float*)d_in[1];
    const float* theta = (const float*)d_in[2];
    const float* Wh    = (const float*)d_in[3];
    const float* Wt    = (const float*)d_in[4];
    const float* bt    = (const float*)d_in[5];
    float* out = (float*)d_out;

    // Opt-in to >48KB dynamic smem (host-side attribute, immediate; capture-safe)
    cudaFuncSetAttribute(k_gemm_mma, cudaFuncAttributeMaxDynamicSharedMemorySize, GEMM_SMEM);

    k_split_x<<<MM * DD / 4 / 256, 256>>>(x);
    k_prep_w<<<3 * DD * DD / 256, 256>>>(theta, Wh, Wt);
    k_deg_csr<<<512, 256>>>(adj);
    dim3 g2(MM / 128, 6);
    k_gemm_mma<<<g2, 256, GEMM_SMEM>>>(bt);
    k_spmm<<<MM / 4, 256>>>(out);
}

// round 12
// speedup vs baseline: 1.2551x; 1.2551x over previous
#include <cuda_runtime.h>
#include <cuda_bf16.h>
#include <math.h>
#include <stdint.h>

// Problem constants
#define BB    4
#define NN    4096
#define DD    256
#define MM    (BB * NN)        // 16384 flattened rows
#define MAXNZ 128

// ---------------------------------------------------------------------------
// Scratch (static __device__ — no allocations allowed)
// ---------------------------------------------------------------------------
static __device__ float          g_norm[MM];
static __device__ int            g_nnz[MM];
static __device__ int            g_cidx[MM * MAXNZ];
static __device__ float          g_cval[MM * MAXNZ];
static __device__ float          g_h[MM * DD];      // raw x@theta (no norm)
static __device__ float          g_het[MM * DD];    // x@W_h
static __device__ float          g_gate[MM * DD];   // sigmoid(x@W_t + b_t)
static __device__ __nv_bfloat16  g_xhi[MM * DD];
static __device__ __nv_bfloat16  g_xlo[MM * DD];
// W^T splits: [mat][hi/lo][n][k], each DD*DD
static __device__ __nv_bfloat16  g_wt[3 * 2 * DD * DD];

// ---------------------------------------------------------------------------
// PTX helpers (plain sm_100 target: mma.sync / ldmatrix / cp.async)
// ---------------------------------------------------------------------------
__device__ __forceinline__ uint32_t smem_u32(const void* p) {
    uint32_t a;
    asm("{ .reg .u64 t; cvta.to.shared.u64 t, %1; cvt.u32.u64 %0, t; }" : "=r"(a) : "l"(p));
    return a;
}
__device__ __forceinline__ void cp16(uint32_t dst, const void* src) {
    asm volatile("cp.async.cg.shared.global [%0], [%1], 16;" :: "r"(dst), "l"(src));
}
#define CP_COMMIT() asm volatile("cp.async.commit_group;" ::: "memory")
#define CP_WAIT(n)  asm volatile("cp.async.wait_group %0;" :: "n"(n) : "memory")

__device__ __forceinline__ void ldsm4(uint32_t* r, uint32_t a) {
    asm volatile("ldmatrix.sync.aligned.m8n8.x4.shared.b16 {%0,%1,%2,%3}, [%4];"
        : "=r"(r[0]), "=r"(r[1]), "=r"(r[2]), "=r"(r[3]) : "r"(a));
}
__device__ __forceinline__ void mma16816(float* d, const uint32_t* a, const uint32_t* b) {
    asm volatile(
        "mma.sync.aligned.m16n8k16.row.col.f32.bf16.bf16.f32 "
        "{%0,%1,%2,%3}, {%4,%5,%6,%7}, {%8,%9}, {%0,%1,%2,%3};"
        : "+f"(d[0]), "+f"(d[1]), "+f"(d[2]), "+f"(d[3])
        : "r"(a[0]), "r"(a[1]), "r"(a[2]), "r"(a[3]), "r"(b[0]), "r"(b[1]));
}

// SW128 swizzle for 128B rows: bank-rotate 16B chunks by row within 8-row group
__device__ __forceinline__ int swz128(int row, int intra) {
    return row * 128 + (intra ^ ((row & 7) * 16));
}

// ---------------------------------------------------------------------------
// K0a: split x into bf16 hi/lo
// ---------------------------------------------------------------------------
__global__ __launch_bounds__(256) void k_split_x(const float* __restrict__ x) {
    int i = blockIdx.x * blockDim.x + threadIdx.x;   // over MM*DD/4
    float4 v = ((const float4*)x)[i];
    __nv_bfloat16 hx = __float2bfloat16(v.x), hy = __float2bfloat16(v.y);
    __nv_bfloat16 hz = __float2bfloat16(v.z), hw = __float2bfloat16(v.w);
    __nv_bfloat16 lx = __float2bfloat16(v.x - __bfloat162float(hx));
    __nv_bfloat16 ly = __float2bfloat16(v.y - __bfloat162float(hy));
    __nv_bfloat16 lz = __float2bfloat16(v.z - __bfloat162float(hz));
    __nv_bfloat16 lw = __float2bfloat16(v.w - __bfloat162float(hw));
    __nv_bfloat162* ph = (__nv_bfloat162*)&g_xhi[i * 4];
    __nv_bfloat162* pl = (__nv_bfloat162*)&g_xlo[i * 4];
    ph[0] = __nv_bfloat162(hx, hy); ph[1] = __nv_bfloat162(hz, hw);
    pl[0] = __nv_bfloat162(lx, ly); pl[1] = __nv_bfloat162(lz, lw);
}

// ---------------------------------------------------------------------------
// K0b: build W^T hi/lo for the 3 weight matrices
// ---------------------------------------------------------------------------
__global__ __launch_bounds__(256) void k_prep_w(const float* __restrict__ theta,
                                                const float* __restrict__ Wh,
                                                const float* __restrict__ Wt) {
    int i = blockIdx.x * blockDim.x + threadIdx.x;   // over 3*DD*DD
    int mat = i >> 16;
    int r   = i & 65535;
    int n   = r >> 8;
    int k   = r & 255;
    const float* W = (mat == 0) ? theta : (mat == 1) ? Wh : Wt;
    float v = W[k * DD + n];
    __nv_bfloat16 hi = __float2bfloat16(v);
    __nv_bfloat16 lo = __float2bfloat16(v - __bfloat162float(hi));
    g_wt[((size_t)(mat * 2 + 0) << 16) + n * DD + k] = hi;
    g_wt[((size_t)(mat * 2 + 1) << 16) + n * DD + k] = lo;
}

// ---------------------------------------------------------------------------
// K1: CSR extraction (R9 shfl-scan version — ballot variant regressed in R10).
// 4 rows per warp, batches of 8 float4 loads in flight. HBM-bound.
// ---------------------------------------------------------------------------
__global__ __launch_bounds__(256) void k_deg_csr(const float* __restrict__ adj) {
    const int wid  = threadIdx.x >> 5;
    const int lane = threadIdx.x & 31;
    const int wbase = (blockIdx.x * 8 + wid) * 4;
    for (int rr = 0; rr < 4; ++rr) {
        const int w = wbase + rr;
        const float4* rowp = (const float4*)(adj + (size_t)w * NN);
        const int base_out = w * MAXNZ;
        const int bbase    = w & ~(NN - 1);
        float degacc = 0.f;
        int   cnt    = 0;
        for (int it4 = 0; it4 < 4; ++it4) {
            float4 v[8];
            #pragma unroll
            for (int j = 0; j < 8; ++j)
                v[j] = rowp[it4 * 256 + j * 32 + lane];
            #pragma unroll
            for (int j = 0; j < 8; ++j) {
                degacc += fabsf(v[j].x) + fabsf(v[j].y) + fabsf(v[j].z) + fabsf(v[j].w);
                int lc = (v[j].x != 0.f) + (v[j].y != 0.f) + (v[j].z != 0.f) + (v[j].w != 0.f);
                int scan = lc;
                #pragma unroll
                for (int o = 1; o < 32; o <<= 1) {
                    int t = __shfl_up_sync(0xffffffffu, scan, o);
                    if (lane >= o) scan += t;
                }
                int pos = cnt + (scan - lc);
                int col = bbase + (it4 * 8 + j) * 128 + lane * 4;
                if (v[j].x != 0.f && pos < MAXNZ) { g_cidx[base_out + pos] = col + 0; g_cval[base_out + pos] = v[j].x; pos++; }
                if (v[j].y != 0.f && pos < MAXNZ) { g_cidx[base_out + pos] = col + 1; g_cval[base_out + pos] = v[j].y; pos++; }
                if (v[j].z != 0.f && pos < MAXNZ) { g_cidx[base_out + pos] = col + 2; g_cval[base_out + pos] = v[j].z; pos++; }
                if (v[j].w != 0.f && pos < MAXNZ) { g_cidx[base_out + pos] = col + 3; g_cval[base_out + pos] = v[j].w; pos++; }
                cnt += __shfl_sync(0xffffffffu, scan, 31);
            }
        }
        #pragma unroll
        for (int o = 16; o; o >>= 1)
            degacc += __shfl_xor_sync(0xffffffffu, degacc, o);
        if (lane == 0) {
            g_nnz[w]  = cnt < MAXNZ ? cnt : MAXNZ;
            g_norm[w] = rsqrtf(degacc + 1e-6f);
        }
    }
}

// ---------------------------------------------------------------------------
// K2: bf16-split GEMM via mma.sync.m16n8k16.
// CTA tile 128x128 (8 warps: 4m x 2n). BK=64, 3-stage cp.async ring (96KB
// dynamic smem), one __syncthreads per iteration.
// Segments: mats 0/1 (theta, W_h) use 3-term split (12 iters);
// mat 2 (W_t, gate) is sigmoid-damped -> single hi*hi pass (4 iters).
// ---------------------------------------------------------------------------
#define TILE_B   (128 * 128)         // 16384 bytes per tile (A or B)
#define STAGE_B  (2 * TILE_B)        // 32768
#define GEMM_SMEM (3 * STAGE_B)      // 98304

__global__ __launch_bounds__(256, 2) void k_gemm_mma(const float* __restrict__ bt) {
    extern __shared__ __align__(128) char sm[];

    const int tid  = threadIdx.x;
    const int wid  = tid >> 5;
    const int lane = tid & 31;
    const int wm   = wid & 3;
    const int wn   = wid >> 2;
    const int g    = lane >> 3;
    const int lr   = lane & 7;

    const int mat   = blockIdx.y >> 1;
    const int nhalf = blockIdx.y & 1;
    const int m0    = blockIdx.x * 128;
    const int n0    = nhalf * 128;
    const __nv_bfloat16* wt_hi = g_wt + ((size_t)(mat * 2) << 16);
    const __nv_bfloat16* wt_lo = wt_hi + (1 << 16);

    const int niter = (mat == 2) ? 4 : 12;   // gate: single-pass bf16

    const uint32_t smb = smem_u32(sm);

    float acc[2][8][4] = {};

    // One stage = full 64-wide K slab of A and B (each 128 rows x 128B).
    auto load_stage = [&](int iter, int stage) {
        const int seg = iter >> 2;              // segs of 4 iterations
        const int k0  = (iter & 3) * 64;
        const __nv_bfloat16* Asrc = (seg < 2) ? g_xhi : g_xlo;
        const __nv_bfloat16* Bsrc = (seg == 1) ? wt_lo : wt_hi;
        const uint32_t sa = smb + stage * STAGE_B;
        const uint32_t sb = sa + TILE_B;
        #pragma unroll
        for (int j = 0; j < 4; ++j) {
            int id  = tid + j * 256;            // 0..1023
            int row = id >> 3, c = id & 7;
            int so  = swz128(row, c * 16);
            cp16(sa + so, Asrc + (size_t)(m0 + row) * DD + k0 + c * 8);
            cp16(sb + so, Bsrc + (size_t)(n0 + row) * DD + k0 + c * 8);
        }
        CP_COMMIT();
    };

    // ldmatrix offsets for ks in [0,4): intra = ks*32 + half*16, swizzled.
    int aoff[2][4], boff[4][4];
    #pragma unroll
    for (int mi = 0; mi < 2; ++mi) {
        int r = wm * 32 + mi * 16 + (g & 1) * 8 + lr;
        #pragma unroll
        for (int ks = 0; ks < 4; ++ks)
            aoff[mi][ks] = swz128(r, ks * 32 + (g >> 1) * 16);
    }
    #pragma unroll
    for (int nt = 0; nt < 4; ++nt) {
        int r = wn * 64 + nt * 16 + (g >> 1) * 8 + lr;
        #pragma unroll
        for (int ks = 0; ks < 4; ++ks)
            boff[nt][ks] = swz128(r, ks * 32 + (g & 1) * 16);
    }

    load_stage(0, 0);
    load_stage(1, 1);

    int stage = 0;
    for (int it = 0; it < niter; ++it) {
        CP_WAIT(1);
        __syncthreads();

        if (it + 2 < niter) load_stage(it + 2, (stage + 2) % 3);

        const uint32_t sa = smb + stage * STAGE_B;
        const uint32_t sb = sa + TILE_B;

        #pragma unroll
        for (int ks = 0; ks < 4; ++ks) {
            uint32_t afrag[2][4], bfrag[4][4];
            #pragma unroll
            for (int mi = 0; mi < 2; ++mi)
                ldsm4(afrag[mi], sa + aoff[mi][ks]);
            #pragma unroll
            for (int nt = 0; nt < 4; ++nt)
                ldsm4(bfrag[nt], sb + boff[nt][ks]);
            #pragma unroll
            for (int mi = 0; mi < 2; ++mi)
                #pragma unroll
                for (int ni = 0; ni < 8; ++ni)
                    mma16816(acc[mi][ni], afrag[mi], &bfrag[ni >> 1][(ni & 1) * 2]);
        }
        stage = (stage + 1) % 3;
    }

    float* dst = (mat == 0) ? g_h : (mat == 1) ? g_het : g_gate;
    #pragma unroll
    for (int mi = 0; mi < 2; ++mi) {
        #pragma unroll
        for (int rh = 0; rh < 2; ++rh) {
            const int r = m0 + wm * 32 + mi * 16 + rh * 8 + (lane >> 2);
            #pragma unroll
            for (int ni = 0; ni < 8; ++ni) {
                const int c = n0 + wn * 64 + ni * 8 + (lane & 3) * 2;
                float v0 = acc[mi][ni][rh * 2];
                float v1 = acc[mi][ni][rh * 2 + 1];
                if (mat == 2) {
                    v0 = 1.f / (1.f + expf(-(v0 + bt[c])));
                    v1 = 1.f / (1.f + expf(-(v1 + bt[c + 1])));
                }
                *(float2*)(dst + (size_t)r * DD + c) = make_float2(v0, v1);
            }
        }
    }
}

// ---------------------------------------------------------------------------
// K3: vectorized sparse gather + gate/combine + ELU.
// 4 rows per block, 64 threads per row, float4 per thread.
// ---------------------------------------------------------------------------
__global__ __launch_bounds__(256) void k_spmm(float* __restrict__ out) {
    const int grp = threadIdx.x >> 6;     // row within block (0..3)
    const int ch  = threadIdx.x & 63;     // channel group (x4)
    const int row = blockIdx.x * 4 + grp;

    __shared__ int   soff[4][MAXNZ];
    __shared__ float sval[4][MAXNZ];

    const int nnz = g_nnz[row];
    #pragma unroll
    for (int j = 0; j < 2; ++j) {
        int e = ch + j * 64;
        if (e < nnz) {
            int o = row * MAXNZ + e;
            int s = g_cidx[o];
            soff[grp][e] = s * DD;
            sval[grp][e] = g_cval[o] * g_norm[s];
        }
    }
    __syncthreads();

    const float* hbase = g_h + ch * 4;
    float4 acc = make_float4(0.f, 0.f, 0.f, 0.f);
    int e = 0;
    #pragma unroll 1
    for (; e + 4 <= nnz; e += 4) {
        float4 h0 = *(const float4*)(hbase + soff[grp][e]);
        float4 h1 = *(const float4*)(hbase + soff[grp][e + 1]);
        float4 h2 = *(const float4*)(hbase + soff[grp][e + 2]);
        float4 h3 = *(const float4*)(hbase + soff[grp][e + 3]);
        float v0 = sval[grp][e],     v1 = sval[grp][e + 1];
        float v2 = sval[grp][e + 2], v3 = sval[grp][e + 3];
        acc.x += v0 * h0.x; acc.y += v0 * h0.y; acc.z += v0 * h0.z; acc.w += v0 * h0.w;
        acc.x += v1 * h1.x; acc.y += v1 * h1.y; acc.z += v1 * h1.z; acc.w += v1 * h1.w;
        acc.x += v2 * h2.x; acc.y += v2 * h2.y; acc.z += v2 * h2.z; acc.w += v2 * h2.w;
        acc.x += v3 * h3.x; acc.y += v3 * h3.y; acc.z += v3 * h3.z; acc.w += v3 * h3.w;
    }
    for (; e < nnz; ++e) {
        float v = sval[grp][e];
        float4 hv = *(const float4*)(hbase + soff[grp][e]);
        acc.x += v * hv.x; acc.y += v * hv.y; acc.z += v * hv.z; acc.w += v * hv.w;
    }

    const size_t o = (size_t)row * DD + ch * 4;
    const float nrm = g_norm[row];
    float4 gt = *(const float4*)(g_gate + o);
    float4 ht = *(const float4*)(g_het + o);
    float4 f;
    f.x = gt.x * (acc.x * nrm) + (1.f - gt.x) * ht.x;
    f.y = gt.y * (acc.y * nrm) + (1.f - gt.y) * ht.y;
    f.z = gt.z * (acc.z * nrm) + (1.f - gt.z) * ht.z;
    f.w = gt.w * (acc.w * nrm) + (1.f - gt.w) * ht.w;
    f.x = f.x > 0.f ? f.x : expm1f(f.x);
    f.y = f.y > 0.f ? f.y : expm1f(f.y);
    f.z = f.z > 0.f ? f.z : expm1f(f.z);
    f.w = f.w > 0.f ? f.w : expm1f(f.w);
    *(float4*)(out + o) = f;
}

// ---------------------------------------------------------------------------
extern "C" void kernel_launch(void* const* d_in, const int* in_sizes, int n_in,
                              void* d_out, int out_size) {
    const float* x     = (const float*)d_in[0];
    const float* adj   = (const float*)d_in[1];
    const float* theta = (const float*)d_in[2];
    const float* Wh    = (const float*)d_in[3];
    const float* Wt    = (const float*)d_in[4];
    const float* bt    = (const float*)d_in[5];
    float* out = (float*)d_out;

    // Opt-in to >48KB dynamic smem (host-side attribute, immediate; capture-safe)
    cudaFuncSetAttribute(k_gemm_mma, cudaFuncAttributeMaxDynamicSharedMemorySize, GEMM_SMEM);

    k_split_x<<<MM * DD / 4 / 256, 256>>>(x);
    k_prep_w<<<3 * DD * DD / 256, 256>>>(theta, Wh, Wt);
    k_deg_csr<<<512, 256>>>(adj);
    dim3 g2(MM / 128, 6);
    k_gemm_mma<<<g2, 256, GEMM_SMEM>>>(bt);
    k_spmm<<<MM / 4, 256>>>(out);
}

// round 13
// speedup vs baseline: 1.2697x; 1.0116x over previous
#include <cuda_runtime.h>
#include <cuda_bf16.h>
#include <math.h>
#include <stdint.h>

// Problem constants
#define BB    4
#define NN    4096
#define DD    256
#define MM    (BB * NN)        // 16384 flattened rows
#define MAXNZ 128

// ---------------------------------------------------------------------------
// Scratch (static __device__ — no allocations allowed)
// ---------------------------------------------------------------------------
static __device__ float          g_norm[MM];
static __device__ int            g_nnz[MM];
static __device__ int            g_cidx[MM * MAXNZ];
static __device__ float          g_cval[MM * MAXNZ];
static __device__ float          g_h[MM * DD];      // raw x@theta (no norm)
static __device__ float          g_het[MM * DD];    // x@W_h
static __device__ float          g_gate[MM * DD];   // sigmoid(x@W_t + b_t)
static __device__ __nv_bfloat16  g_xhi[MM * DD];
static __device__ __nv_bfloat16  g_xlo[MM * DD];
// W^T splits: [mat][hi/lo][n][k], each DD*DD
static __device__ __nv_bfloat16  g_wt[3 * 2 * DD * DD];

// ---------------------------------------------------------------------------
// PTX helpers (plain sm_100 target: mma.sync / ldmatrix / cp.async)
// ---------------------------------------------------------------------------
__device__ __forceinline__ uint32_t smem_u32(const void* p) {
    uint32_t a;
    asm("{ .reg .u64 t; cvta.to.shared.u64 t, %1; cvt.u32.u64 %0, t; }" : "=r"(a) : "l"(p));
    return a;
}
__device__ __forceinline__ void cp16(uint32_t dst, const void* src) {
    asm volatile("cp.async.cg.shared.global [%0], [%1], 16;" :: "r"(dst), "l"(src));
}
#define CP_COMMIT() asm volatile("cp.async.commit_group;" ::: "memory")
#define CP_WAIT(n)  asm volatile("cp.async.wait_group %0;" :: "n"(n) : "memory")

__device__ __forceinline__ void ldsm4(uint32_t* r, uint32_t a) {
    asm volatile("ldmatrix.sync.aligned.m8n8.x4.shared.b16 {%0,%1,%2,%3}, [%4];"
        : "=r"(r[0]), "=r"(r[1]), "=r"(r[2]), "=r"(r[3]) : "r"(a));
}
__device__ __forceinline__ void mma16816(float* d, const uint32_t* a, const uint32_t* b) {
    asm volatile(
        "mma.sync.aligned.m16n8k16.row.col.f32.bf16.bf16.f32 "
        "{%0,%1,%2,%3}, {%4,%5,%6,%7}, {%8,%9}, {%0,%1,%2,%3};"
        : "+f"(d[0]), "+f"(d[1]), "+f"(d[2]), "+f"(d[3])
        : "r"(a[0]), "r"(a[1]), "r"(a[2]), "r"(a[3]), "r"(b[0]), "r"(b[1]));
}

// SW128 swizzle for 128B rows: bank-rotate 16B chunks by row within 8-row group
__device__ __forceinline__ int swz128(int row, int intra) {
    return row * 128 + (intra ^ ((row & 7) * 16));
}

// ---------------------------------------------------------------------------
// K0a: split x into bf16 hi/lo
// ---------------------------------------------------------------------------
__global__ __launch_bounds__(256) void k_split_x(const float* __restrict__ x) {
    int i = blockIdx.x * blockDim.x + threadIdx.x;   // over MM*DD/4
    float4 v = ((const float4*)x)[i];
    __nv_bfloat16 hx = __float2bfloat16(v.x), hy = __float2bfloat16(v.y);
    __nv_bfloat16 hz = __float2bfloat16(v.z), hw = __float2bfloat16(v.w);
    __nv_bfloat16 lx = __float2bfloat16(v.x - __bfloat162float(hx));
    __nv_bfloat16 ly = __float2bfloat16(v.y - __bfloat162float(hy));
    __nv_bfloat16 lz = __float2bfloat16(v.z - __bfloat162float(hz));
    __nv_bfloat16 lw = __float2bfloat16(v.w - __bfloat162float(hw));
    __nv_bfloat162* ph = (__nv_bfloat162*)&g_xhi[i * 4];
    __nv_bfloat162* pl = (__nv_bfloat162*)&g_xlo[i * 4];
    ph[0] = __nv_bfloat162(hx, hy); ph[1] = __nv_bfloat162(hz, hw);
    pl[0] = __nv_bfloat162(lx, ly); pl[1] = __nv_bfloat162(lz, lw);
}

// ---------------------------------------------------------------------------
// K0b: build W^T hi/lo for the 3 weight matrices
// ---------------------------------------------------------------------------
__global__ __launch_bounds__(256) void k_prep_w(const float* __restrict__ theta,
                                                const float* __restrict__ Wh,
                                                const float* __restrict__ Wt) {
    int i = blockIdx.x * blockDim.x + threadIdx.x;   // over 3*DD*DD
    int mat = i >> 16;
    int r   = i & 65535;
    int n   = r >> 8;
    int k   = r & 255;
    const float* W = (mat == 0) ? theta : (mat == 1) ? Wh : Wt;
    float v = W[k * DD + n];
    __nv_bfloat16 hi = __float2bfloat16(v);
    __nv_bfloat16 lo = __float2bfloat16(v - __bfloat162float(hi));
    g_wt[((size_t)(mat * 2 + 0) << 16) + n * DD + k] = hi;
    g_wt[((size_t)(mat * 2 + 1) << 16) + n * DD + k] = lo;
}

// ---------------------------------------------------------------------------
// K1: CSR extraction with BATCHED scan: one warp scan per 8-float4 batch
// (4 scans per row instead of 32). Each lane reserves a contiguous block of
// positions for all its candidates in the batch (lane-major order across the
// batch — SpMM reduction is order-independent; degacc math unchanged).
// 4 rows per warp, 8 float4 loads in flight. HBM-bound target ~80% DRAM.
// ---------------------------------------------------------------------------
__global__ __launch_bounds__(256) void k_deg_csr(const float* __restrict__ adj) {
    const int wid  = threadIdx.x >> 5;
    const int lane = threadIdx.x & 31;
    const int wbase = (blockIdx.x * 8 + wid) * 4;
    for (int rr = 0; rr < 4; ++rr) {
        const int w = wbase + rr;
        const float4* rowp = (const float4*)(adj + (size_t)w * NN);
        const int base_out = w * MAXNZ;
        const int bbase    = w & ~(NN - 1);
        float degacc = 0.f;
        int   cnt    = 0;
        for (int it4 = 0; it4 < 4; ++it4) {
            float4 v[8];
            #pragma unroll
            for (int j = 0; j < 8; ++j)
                v[j] = rowp[it4 * 256 + j * 32 + lane];

            // Pass 1: degree + total candidate count for this lane over batch
            int lct = 0;
            #pragma unroll
            for (int j = 0; j < 8; ++j) {
                degacc += fabsf(v[j].x) + fabsf(v[j].y) + fabsf(v[j].z) + fabsf(v[j].w);
                lct += (v[j].x != 0.f) + (v[j].y != 0.f) + (v[j].z != 0.f) + (v[j].w != 0.f);
            }

            // ONE warp inclusive scan of lct
            int scan = lct;
            #pragma unroll
            for (int o = 1; o < 32; o <<= 1) {
                int t = __shfl_up_sync(0xffffffffu, scan, o);
                if (lane >= o) scan += t;
            }
            int pos = cnt + (scan - lct);
            cnt += __shfl_sync(0xffffffffu, scan, 31);

            // Pass 2: write candidates into the lane's contiguous reservation
            if (lct > 0) {
                #pragma unroll
                for (int j = 0; j < 8; ++j) {
                    int col = bbase + (it4 * 8 + j) * 128 + lane * 4;
                    if (v[j].x != 0.f && pos < MAXNZ) { g_cidx[base_out + pos] = col + 0; g_cval[base_out + pos] = v[j].x; pos++; }
                    if (v[j].y != 0.f && pos < MAXNZ) { g_cidx[base_out + pos] = col + 1; g_cval[base_out + pos] = v[j].y; pos++; }
                    if (v[j].z != 0.f && pos < MAXNZ) { g_cidx[base_out + pos] = col + 2; g_cval[base_out + pos] = v[j].z; pos++; }
                    if (v[j].w != 0.f && pos < MAXNZ) { g_cidx[base_out + pos] = col + 3; g_cval[base_out + pos] = v[j].w; pos++; }
                }
            }
        }
        #pragma unroll
        for (int o = 16; o; o >>= 1)
            degacc += __shfl_xor_sync(0xffffffffu, degacc, o);
        if (lane == 0) {
            g_nnz[w]  = cnt < MAXNZ ? cnt : MAXNZ;
            g_norm[w] = rsqrtf(degacc + 1e-6f);
        }
    }
}

// ---------------------------------------------------------------------------
// K2: bf16-split GEMM via mma.sync.m16n8k16.
// CTA tile 128x128 (8 warps: 4m x 2n). BK=64, 3-stage cp.async ring (96KB
// dynamic smem), one __syncthreads per iteration.
// Segments: mats 0/1 (theta, W_h) use 3-term split (12 iters);
// mat 2 (W_t, gate) is sigmoid-damped -> single hi*hi pass (4 iters).
// ---------------------------------------------------------------------------
#define TILE_B   (128 * 128)         // 16384 bytes per tile (A or B)
#define STAGE_B  (2 * TILE_B)        // 32768
#define GEMM_SMEM (3 * STAGE_B)      // 98304

__global__ __launch_bounds__(256, 2) void k_gemm_mma(const float* __restrict__ bt) {
    extern __shared__ __align__(128) char sm[];

    const int tid  = threadIdx.x;
    const int wid  = tid >> 5;
    const int lane = tid & 31;
    const int wm   = wid & 3;
    const int wn   = wid >> 2;
    const int g    = lane >> 3;
    const int lr   = lane & 7;

    const int mat   = blockIdx.y >> 1;
    const int nhalf = blockIdx.y & 1;
    const int m0    = blockIdx.x * 128;
    const int n0    = nhalf * 128;
    const __nv_bfloat16* wt_hi = g_wt + ((size_t)(mat * 2) << 16);
    const __nv_bfloat16* wt_lo = wt_hi + (1 << 16);

    const int niter = (mat == 2) ? 4 : 12;   // gate: single-pass bf16

    const uint32_t smb = smem_u32(sm);

    float acc[2][8][4] = {};

    // One stage = full 64-wide K slab of A and B (each 128 rows x 128B).
    auto load_stage = [&](int iter, int stage) {
        const int seg = iter >> 2;              // segs of 4 iterations
        const int k0  = (iter & 3) * 64;
        const __nv_bfloat16* Asrc = (seg < 2) ? g_xhi : g_xlo;
        const __nv_bfloat16* Bsrc = (seg == 1) ? wt_lo : wt_hi;
        const uint32_t sa = smb + stage * STAGE_B;
        const uint32_t sb = sa + TILE_B;
        #pragma unroll
        for (int j = 0; j < 4; ++j) {
            int id  = tid + j * 256;            // 0..1023
            int row = id >> 3, c = id & 7;
            int so  = swz128(row, c * 16);
            cp16(sa + so, Asrc + (size_t)(m0 + row) * DD + k0 + c * 8);
            cp16(sb + so, Bsrc + (size_t)(n0 + row) * DD + k0 + c * 8);
        }
        CP_COMMIT();
    };

    // ldmatrix offsets for ks in [0,4): intra = ks*32 + half*16, swizzled.
    int aoff[2][4], boff[4][4];
    #pragma unroll
    for (int mi = 0; mi < 2; ++mi) {
        int r = wm * 32 + mi * 16 + (g & 1) * 8 + lr;
        #pragma unroll
        for (int ks = 0; ks < 4; ++ks)
            aoff[mi][ks] = swz128(r, ks * 32 + (g >> 1) * 16);
    }
    #pragma unroll
    for (int nt = 0; nt < 4; ++nt) {
        int r = wn * 64 + nt * 16 + (g >> 1) * 8 + lr;
        #pragma unroll
        for (int ks = 0; ks < 4; ++ks)
            boff[nt][ks] = swz128(r, ks * 32 + (g & 1) * 16);
    }

    load_stage(0, 0);
    load_stage(1, 1);

    int stage = 0;
    for (int it = 0; it < niter; ++it) {
        CP_WAIT(1);
        __syncthreads();

        if (it + 2 < niter) load_stage(it + 2, (stage + 2) % 3);

        const uint32_t sa = smb + stage * STAGE_B;
        const uint32_t sb = sa + TILE_B;

        #pragma unroll
        for (int ks = 0; ks < 4; ++ks) {
            uint32_t afrag[2][4], bfrag[4][4];
            #pragma unroll
            for (int mi = 0; mi < 2; ++mi)
                ldsm4(afrag[mi], sa + aoff[mi][ks]);
            #pragma unroll
            for (int nt = 0; nt < 4; ++nt)
                ldsm4(bfrag[nt], sb + boff[nt][ks]);
            #pragma unroll
            for (int mi = 0; mi < 2; ++mi)
                #pragma unroll
                for (int ni = 0; ni < 8; ++ni)
                    mma16816(acc[mi][ni], afrag[mi], &bfrag[ni >> 1][(ni & 1) * 2]);
        }
        stage = (stage + 1) % 3;
    }

    float* dst = (mat == 0) ? g_h : (mat == 1) ? g_het : g_gate;
    #pragma unroll
    for (int mi = 0; mi < 2; ++mi) {
        #pragma unroll
        for (int rh = 0; rh < 2; ++rh) {
            const int r = m0 + wm * 32 + mi * 16 + rh * 8 + (lane >> 2);
            #pragma unroll
            for (int ni = 0; ni < 8; ++ni) {
                const int c = n0 + wn * 64 + ni * 8 + (lane & 3) * 2;
                float v0 = acc[mi][ni][rh * 2];
                float v1 = acc[mi][ni][rh * 2 + 1];
                if (mat == 2) {
                    v0 = 1.f / (1.f + expf(-(v0 + bt[c])));
                    v1 = 1.f / (1.f + expf(-(v1 + bt[c + 1])));
                }
                *(float2*)(dst + (size_t)r * DD + c) = make_float2(v0, v1);
            }
        }
    }
}

// ---------------------------------------------------------------------------
// K3: vectorized sparse gather + gate/combine + ELU.
// 4 rows per block, 64 threads per row, float4 per thread.
// ---------------------------------------------------------------------------
__global__ __launch_bounds__(256) void k_spmm(float* __restrict__ out) {
    const int grp = threadIdx.x >> 6;     // row within block (0..3)
    const int ch  = threadIdx.x & 63;     // channel group (x4)
    const int row = blockIdx.x * 4 + grp;

    __shared__ int   soff[4][MAXNZ];
    __shared__ float sval[4][MAXNZ];

    const int nnz = g_nnz[row];
    #pragma unroll
    for (int j = 0; j < 2; ++j) {
        int e = ch + j * 64;
        if (e < nnz) {
            int o = row * MAXNZ + e;
            int s = g_cidx[o];
            soff[grp][e] = s * DD;
            sval[grp][e] = g_cval[o] * g_norm[s];
        }
    }
    __syncthreads();

    const float* hbase = g_h + ch * 4;
    float4 acc = make_float4(0.f, 0.f, 0.f, 0.f);
    int e = 0;
    #pragma unroll 1
    for (; e + 4 <= nnz; e += 4) {
        float4 h0 = *(const float4*)(hbase + soff[grp][e]);
        float4 h1 = *(const float4*)(hbase + soff[grp][e + 1]);
        float4 h2 = *(const float4*)(hbase + soff[grp][e + 2]);
        float4 h3 = *(const float4*)(hbase + soff[grp][e + 3]);
        float v0 = sval[grp][e],     v1 = sval[grp][e + 1];
        float v2 = sval[grp][e + 2], v3 = sval[grp][e + 3];
        acc.x += v0 * h0.x; acc.y += v0 * h0.y; acc.z += v0 * h0.z; acc.w += v0 * h0.w;
        acc.x += v1 * h1.x; acc.y += v1 * h1.y; acc.z += v1 * h1.z; acc.w += v1 * h1.w;
        acc.x += v2 * h2.x; acc.y += v2 * h2.y; acc.z += v2 * h2.z; acc.w += v2 * h2.w;
        acc.x += v3 * h3.x; acc.y += v3 * h3.y; acc.z += v3 * h3.z; acc.w += v3 * h3.w;
    }
    for (; e < nnz; ++e) {
        float v = sval[grp][e];
        float4 hv = *(const float4*)(hbase + soff[grp][e]);
        acc.x += v * hv.x; acc.y += v * hv.y; acc.z += v * hv.z; acc.w += v * hv.w;
    }

    const size_t o = (size_t)row * DD + ch * 4;
    const float nrm = g_norm[row];
    float4 gt = *(const float4*)(g_gate + o);
    float4 ht = *(const float4*)(g_het + o);
    float4 f;
    f.x = gt.x * (acc.x * nrm) + (1.f - gt.x) * ht.x;
    f.y = gt.y * (acc.y * nrm) + (1.f - gt.y) * ht.y;
    f.z = gt.z * (acc.z * nrm) + (1.f - gt.z) * ht.z;
    f.w = gt.w * (acc.w * nrm) + (1.f - gt.w) * ht.w;
    f.x = f.x > 0.f ? f.x : expm1f(f.x);
    f.y = f.y > 0.f ? f.y : expm1f(f.y);
    f.z = f.z > 0.f ? f.z : expm1f(f.z);
    f.w = f.w > 0.f ? f.w : expm1f(f.w);
    *(float4*)(out + o) = f;
}

// ---------------------------------------------------------------------------
extern "C" void kernel_launch(void* const* d_in, const int* in_sizes, int n_in,
                              void* d_out, int out_size) {
    const float* x     = (const float*)d_in[0];
    const float* adj   = (const float*)d_in[1];
    const float* theta = (const float*)d_in[2];
    const float* Wh    = (const float*)d_in[3];
    const float* Wt    = (const float*)d_in[4];
    const float* bt    = (const float*)d_in[5];
    float* out = (float*)d_out;

    // Opt-in to >48KB dynamic smem (host-side attribute, immediate; capture-safe)
    cudaFuncSetAttribute(k_gemm_mma, cudaFuncAttributeMaxDynamicSharedMemorySize, GEMM_SMEM);

    k_split_x<<<MM * DD / 4 / 256, 256>>>(x);
    k_prep_w<<<3 * DD * DD / 256, 256>>>(theta, Wh, Wt);
    k_deg_csr<<<512, 256>>>(adj);
    dim3 g2(MM / 128, 6);
    k_gemm_mma<<<g2, 256, GEMM_SMEM>>>(bt);
    k_spmm<<<MM / 4, 256>>>(out);
}

// round 16
// speedup vs baseline: 1.3609x; 1.0719x over previous
#include <cuda_runtime.h>
#include <cuda_bf16.h>
#include <math.h>
#include <stdint.h>

// Problem constants
#define BB    4
#define NN    4096
#define DD    256
#define MM    (BB * NN)        // 16384 flattened rows
#define MAXNZ 128

// ---------------------------------------------------------------------------
// Scratch (static __device__ — no allocations allowed)
// ---------------------------------------------------------------------------
static __device__ float          g_norm[MM];
static __device__ int            g_nnz[MM];
static __device__ int            g_cidx[MM * MAXNZ];
static __device__ float          g_cval[MM * MAXNZ];
static __device__ float          g_h[MM * DD];      // raw x@theta (no norm)
static __device__ float          g_het[MM * DD];    // x@W_h
static __device__ float          g_gate[MM * DD];   // sigmoid(x@W_t + b_t)
static __device__ __nv_bfloat16  g_xhi[MM * DD];
static __device__ __nv_bfloat16  g_xlo[MM * DD];
// W^T splits: [mat][hi/lo][n][k], each DD*DD
static __device__ __nv_bfloat16  g_wt[3 * 2 * DD * DD];

// ---------------------------------------------------------------------------
// PTX helpers (plain sm_100 target: mma.sync / ldmatrix / cp.async)
// ---------------------------------------------------------------------------
__device__ __forceinline__ uint32_t smem_u32(const void* p) {
    uint32_t a;
    asm("{ .reg .u64 t; cvta.to.shared.u64 t, %1; cvt.u32.u64 %0, t; }" : "=r"(a) : "l"(p));
    return a;
}
__device__ __forceinline__ void cp16(uint32_t dst, const void* src) {
    asm volatile("cp.async.cg.shared.global [%0], [%1], 16;" :: "r"(dst), "l"(src));
}
#define CP_COMMIT() asm volatile("cp.async.commit_group;" ::: "memory")
#define CP_WAIT(n)  asm volatile("cp.async.wait_group %0;" :: "n"(n) : "memory")

__device__ __forceinline__ void ldsm4(uint32_t* r, uint32_t a) {
    asm volatile("ldmatrix.sync.aligned.m8n8.x4.shared.b16 {%0,%1,%2,%3}, [%4];"
        : "=r"(r[0]), "=r"(r[1]), "=r"(r[2]), "=r"(r[3]) : "r"(a));
}
__device__ __forceinline__ void mma16816(float* d, const uint32_t* a, const uint32_t* b) {
    asm volatile(
        "mma.sync.aligned.m16n8k16.row.col.f32.bf16.bf16.f32 "
        "{%0,%1,%2,%3}, {%4,%5,%6,%7}, {%8,%9}, {%0,%1,%2,%3};"
        : "+f"(d[0]), "+f"(d[1]), "+f"(d[2]), "+f"(d[3])
        : "r"(a[0]), "r"(a[1]), "r"(a[2]), "r"(a[3]), "r"(b[0]), "r"(b[1]));
}

// SW128 swizzle for 128B rows: bank-rotate 16B chunks by row within 8-row group
__device__ __forceinline__ int swz128(int row, int intra) {
    return row * 128 + (intra ^ ((row & 7) * 16));
}

// ---------------------------------------------------------------------------
// K0: merged split-x + prep-w.
// blocks [0, 4096):    split x (MM*DD/4 float4 elements, 256/block)
// blocks [4096, 4864): build W^T hi/lo (3*DD*DD elements, 256/block)
// ---------------------------------------------------------------------------
#define SPLIT_BLOCKS (MM * DD / 4 / 256)       // 4096
#define PREP_BLOCKS  (3 * DD * DD / 256)       // 768

__global__ __launch_bounds__(256) void k_prep(const float* __restrict__ x,
                                              const float* __restrict__ theta,
                                              const float* __restrict__ Wh,
                                              const float* __restrict__ Wt) {
    if (blockIdx.x < SPLIT_BLOCKS) {
        int i = blockIdx.x * blockDim.x + threadIdx.x;   // over MM*DD/4
        float4 v = ((const float4*)x)[i];
        __nv_bfloat16 hx = __float2bfloat16(v.x), hy = __float2bfloat16(v.y);
        __nv_bfloat16 hz = __float2bfloat16(v.z), hw = __float2bfloat16(v.w);
        __nv_bfloat16 lx = __float2bfloat16(v.x - __bfloat162float(hx));
        __nv_bfloat16 ly = __float2bfloat16(v.y - __bfloat162float(hy));
        __nv_bfloat16 lz = __float2bfloat16(v.z - __bfloat162float(hz));
        __nv_bfloat16 lw = __float2bfloat16(v.w - __bfloat162float(hw));
        __nv_bfloat162* ph = (__nv_bfloat162*)&g_xhi[i * 4];
        __nv_bfloat162* pl = (__nv_bfloat162*)&g_xlo[i * 4];
        ph[0] = __nv_bfloat162(hx, hy); ph[1] = __nv_bfloat162(hz, hw);
        pl[0] = __nv_bfloat162(lx, ly); pl[1] = __nv_bfloat162(lz, lw);
    } else {
        int i = (blockIdx.x - SPLIT_BLOCKS) * blockDim.x + threadIdx.x;  // over 3*DD*DD
        int mat = i >> 16;
        int r   = i & 65535;
        int n   = r >> 8;
        int k   = r & 255;
        const float* W = (mat == 0) ? theta : (mat == 1) ? Wh : Wt;
        float v = W[k * DD + n];
        __nv_bfloat16 hi = __float2bfloat16(v);
        __nv_bfloat16 lo = __float2bfloat16(v - __bfloat162float(hi));
        g_wt[((size_t)(mat * 2 + 0) << 16) + n * DD + k] = hi;
        g_wt[((size_t)(mat * 2 + 1) << 16) + n * DD + k] = lo;
    }
}

// ---------------------------------------------------------------------------
// K1: CSR extraction, ONE row per warp (2048 blocks x 8 warps = 16384 rows).
// 4x more resident CTAs than the 4-rows/warp version -> more outstanding
// loads -> higher DRAM%. Batched scan: one warp scan per 8-float4 batch.
// ---------------------------------------------------------------------------
__global__ __launch_bounds__(256) void k_deg_csr(const float* __restrict__ adj) {
    const int wid  = threadIdx.x >> 5;
    const int lane = threadIdx.x & 31;
    const int w    = blockIdx.x * 8 + wid;      // one row per warp
    const float4* rowp = (const float4*)(adj + (size_t)w * NN);
    const int base_out = w * MAXNZ;
    const int bbase    = w & ~(NN - 1);
    float degacc = 0.f;
    int   cnt    = 0;
    for (int it4 = 0; it4 < 4; ++it4) {
        float4 v[8];
        #pragma unroll
        for (int j = 0; j < 8; ++j)
            v[j] = rowp[it4 * 256 + j * 32 + lane];

        int lct = 0;
        #pragma unroll
        for (int j = 0; j < 8; ++j) {
            degacc += fabsf(v[j].x) + fabsf(v[j].y) + fabsf(v[j].z) + fabsf(v[j].w);
            lct += (v[j].x != 0.f) + (v[j].y != 0.f) + (v[j].z != 0.f) + (v[j].w != 0.f);
        }

        int scan = lct;
        #pragma unroll
        for (int o = 1; o < 32; o <<= 1) {
            int t = __shfl_up_sync(0xffffffffu, scan, o);
            if (lane >= o) scan += t;
        }
        int pos = cnt + (scan - lct);
        cnt += __shfl_sync(0xffffffffu, scan, 31);

        if (lct > 0) {
            #pragma unroll
            for (int j = 0; j < 8; ++j) {
                int col = bbase + (it4 * 8 + j) * 128 + lane * 4;
                if (v[j].x != 0.f && pos < MAXNZ) { g_cidx[base_out + pos] = col + 0; g_cval[base_out + pos] = v[j].x; pos++; }
                if (v[j].y != 0.f && pos < MAXNZ) { g_cidx[base_out + pos] = col + 1; g_cval[base_out + pos] = v[j].y; pos++; }
                if (v[j].z != 0.f && pos < MAXNZ) { g_cidx[base_out + pos] = col + 2; g_cval[base_out + pos] = v[j].z; pos++; }
                if (v[j].w != 0.f && pos < MAXNZ) { g_cidx[base_out + pos] = col + 3; g_cval[base_out + pos] = v[j].w; pos++; }
            }
        }
    }
    #pragma unroll
    for (int o = 16; o; o >>= 1)
        degacc += __shfl_xor_sync(0xffffffffu, degacc, o);
    if (lane == 0) {
        g_nnz[w]  = cnt < MAXNZ ? cnt : MAXNZ;
        g_norm[w] = rsqrtf(degacc + 1e-6f);
    }
}

// ---------------------------------------------------------------------------
// K2: bf16-split GEMM via mma.sync.m16n8k16.
// CTA tile 128x128 (8 warps: 4m x 2n). BK=64, 3-stage cp.async ring (96KB
// dynamic smem), one __syncthreads per iteration.
// mats 0/1: 3-term split (12 iters); mat 2 (gate): single hi*hi pass (4).
// ---------------------------------------------------------------------------
#define TILE_B   (128 * 128)         // 16384 bytes per tile (A or B)
#define STAGE_B  (2 * TILE_B)        // 32768
#define GEMM_SMEM (3 * STAGE_B)      // 98304

__global__ __launch_bounds__(256, 2) void k_gemm_mma(const float* __restrict__ bt) {
    extern __shared__ __align__(128) char sm[];

    const int tid  = threadIdx.x;
    const int wid  = tid >> 5;
    const int lane = tid & 31;
    const int wm   = wid & 3;
    const int wn   = wid >> 2;
    const int g    = lane >> 3;
    const int lr   = lane & 7;

    const int mat   = blockIdx.y >> 1;
    const int nhalf = blockIdx.y & 1;
    const int m0    = blockIdx.x * 128;
    const int n0    = nhalf * 128;
    const __nv_bfloat16* wt_hi = g_wt + ((size_t)(mat * 2) << 16);
    const __nv_bfloat16* wt_lo = wt_hi + (1 << 16);

    const int niter = (mat == 2) ? 4 : 12;   // gate: single-pass bf16

    const uint32_t smb = smem_u32(sm);

    float acc[2][8][4] = {};

    auto load_stage = [&](int iter, int stage) {
        const int seg = iter >> 2;
        const int k0  = (iter & 3) * 64;
        const __nv_bfloat16* Asrc = (seg < 2) ? g_xhi : g_xlo;
        const __nv_bfloat16* Bsrc = (seg == 1) ? wt_lo : wt_hi;
        const uint32_t sa = smb + stage * STAGE_B;
        const uint32_t sb = sa + TILE_B;
        #pragma unroll
        for (int j = 0; j < 4; ++j) {
            int id  = tid + j * 256;
            int row = id >> 3, c = id & 7;
            int so  = swz128(row, c * 16);
            cp16(sa + so, Asrc + (size_t)(m0 + row) * DD + k0 + c * 8);
            cp16(sb + so, Bsrc + (size_t)(n0 + row) * DD + k0 + c * 8);
        }
        CP_COMMIT();
    };

    int aoff[2][4], boff[4][4];
    #pragma unroll
    for (int mi = 0; mi < 2; ++mi) {
        int r = wm * 32 + mi * 16 + (g & 1) * 8 + lr;
        #pragma unroll
        for (int ks = 0; ks < 4; ++ks)
            aoff[mi][ks] = swz128(r, ks * 32 + (g >> 1) * 16);
    }
    #pragma unroll
    for (int nt = 0; nt < 4; ++nt) {
        int r = wn * 64 + nt * 16 + (g >> 1) * 8 + lr;
        #pragma unroll
        for (int ks = 0; ks < 4; ++ks)
            boff[nt][ks] = swz128(r, ks * 32 + (g & 1) * 16);
    }

    load_stage(0, 0);
    load_stage(1, 1);

    int stage = 0;
    for (int it = 0; it < niter; ++it) {
        CP_WAIT(1);
        __syncthreads();

        if (it + 2 < niter) load_stage(it + 2, (stage + 2) % 3);

        const uint32_t sa = smb + stage * STAGE_B;
        const uint32_t sb = sa + TILE_B;

        #pragma unroll
        for (int ks = 0; ks < 4; ++ks) {
            uint32_t afrag[2][4], bfrag[4][4];
            #pragma unroll
            for (int mi = 0; mi < 2; ++mi)
                ldsm4(afrag[mi], sa + aoff[mi][ks]);
            #pragma unroll
            for (int nt = 0; nt < 4; ++nt)
                ldsm4(bfrag[nt], sb + boff[nt][ks]);
            #pragma unroll
            for (int mi = 0; mi < 2; ++mi)
                #pragma unroll
                for (int ni = 0; ni < 8; ++ni)
                    mma16816(acc[mi][ni], afrag[mi], &bfrag[ni >> 1][(ni & 1) * 2]);
        }
        stage = (stage + 1) % 3;
    }

    float* dst = (mat == 0) ? g_h : (mat == 1) ? g_het : g_gate;
    #pragma unroll
    for (int mi = 0; mi < 2; ++mi) {
        #pragma unroll
        for (int rh = 0; rh < 2; ++rh) {
            const int r = m0 + wm * 32 + mi * 16 + rh * 8 + (lane >> 2);
            #pragma unroll
            for (int ni = 0; ni < 8; ++ni) {
                const int c = n0 + wn * 64 + ni * 8 + (lane & 3) * 2;
                float v0 = acc[mi][ni][rh * 2];
                float v1 = acc[mi][ni][rh * 2 + 1];
                if (mat == 2) {
                    v0 = 1.f / (1.f + expf(-(v0 + bt[c])));
                    v1 = 1.f / (1.f + expf(-(v1 + bt[c + 1])));
                }
                *(float2*)(dst + (size_t)r * DD + c) = make_float2(v0, v1);
            }
        }
    }
}

// ---------------------------------------------------------------------------
// K3: vectorized sparse gather + gate/combine + ELU.
// 4 rows per block, 64 threads per row, float4 per thread. ~L2 roofline.
// ---------------------------------------------------------------------------
__global__ __launch_bounds__(256) void k_spmm(float* __restrict__ out) {
    const int grp = threadIdx.x >> 6;     // row within block (0..3)
    const int ch  = threadIdx.x & 63;     // channel group (x4)
    const int row = blockIdx.x * 4 + grp;

    __shared__ int   soff[4][MAXNZ];
    __shared__ float sval[4][MAXNZ];

    const int nnz = g_nnz[row];
    #pragma unroll
    for (int j = 0; j < 2; ++j) {
        int e = ch + j * 64;
        if (e < nnz) {
            int o = row * MAXNZ + e;
            int s = g_cidx[o];
            soff[grp][e] = s * DD;
            sval[grp][e] = g_cval[o] * g_norm[s];
        }
    }
    __syncthreads();

    const float* hbase = g_h + ch * 4;
    float4 acc = make_float4(0.f, 0.f, 0.f, 0.f);
    int e = 0;
    #pragma unroll 1
    for (; e + 4 <= nnz; e += 4) {
        float4 h0 = *(const float4*)(hbase + soff[grp][e]);
        float4 h1 = *(const float4*)(hbase + soff[grp][e + 1]);
        float4 h2 = *(const float4*)(hbase + soff[grp][e + 2]);
        float4 h3 = *(const float4*)(hbase + soff[grp][e + 3]);
        float v0 = sval[grp][e],     v1 = sval[grp][e + 1];
        float v2 = sval[grp][e + 2], v3 = sval[grp][e + 3];
        acc.x += v0 * h0.x; acc.y += v0 * h0.y; acc.z += v0 * h0.z; acc.w += v0 * h0.w;
        acc.x += v1 * h1.x; acc.y += v1 * h1.y; acc.z += v1 * h1.z; acc.w += v1 * h1.w;
        acc.x += v2 * h2.x; acc.y += v2 * h2.y; acc.z += v2 * h2.z; acc.w += v2 * h2.w;
        acc.x += v3 * h3.x; acc.y += v3 * h3.y; acc.z += v3 * h3.z; acc.w += v3 * h3.w;
    }
    for (; e < nnz; ++e) {
        float v = sval[grp][e];
        float4 hv = *(const float4*)(hbase + soff[grp][e]);
        acc.x += v * hv.x; acc.y += v * hv.y; acc.z += v * hv.z; acc.w += v * hv.w;
    }

    const size_t o = (size_t)row * DD + ch * 4;
    const float nrm = g_norm[row];
    float4 gt = *(const float4*)(g_gate + o);
    float4 ht = *(const float4*)(g_het + o);
    float4 f;
    f.x = gt.x * (acc.x * nrm) + (1.f - gt.x) * ht.x;
    f.y = gt.y * (acc.y * nrm) + (1.f - gt.y) * ht.y;
    f.z = gt.z * (acc.z * nrm) + (1.f - gt.z) * ht.z;
    f.w = gt.w * (acc.w * nrm) + (1.f - gt.w) * ht.w;
    f.x = f.x > 0.f ? f.x : expm1f(f.x);
    f.y = f.y > 0.f ? f.y : expm1f(f.y);
    f.z = f.z > 0.f ? f.z : expm1f(f.z);
    f.w = f.w > 0.f ? f.w : expm1f(f.w);
    *(float4*)(out + o) = f;
}

// ---------------------------------------------------------------------------
// Launch: single stream (fork-join is rejected by this platform — failed 2/2
// with container errors while single-stream always ran).
// ---------------------------------------------------------------------------
extern "C" void kernel_launch(void* const* d_in, const int* in_sizes, int n_in,
                              void* d_out, int out_size) {
    const float* x     = (const float*)d_in[0];
    const float* adj   = (const float*)d_in[1];
    const float* theta = (const float*)d_in[2];
    const float* Wh    = (const float*)d_in[3];
    const float* Wt    = (const float*)d_in[4];
    const float* bt    = (const float*)d_in[5];
    float* out = (float*)d_out;

    // Opt-in to >48KB dynamic smem (host-side attribute, immediate; capture-safe)
    cudaFuncSetAttribute(k_gemm_mma, cudaFuncAttributeMaxDynamicSharedMemorySize, GEMM_SMEM);

    k_prep<<<SPLIT_BLOCKS + PREP_BLOCKS, 256>>>(x, theta, Wh, Wt);
    k_deg_csr<<<2048, 256>>>(adj);
    dim3 g2(MM / 128, 6);
    k_gemm_mma<<<g2, 256, GEMM_SMEM>>>(bt);
    k_spmm<<<MM / 4, 256>>>(out);
}

// round 17
// speedup vs baseline: 1.4074x; 1.0342x over previous
#include <cuda_runtime.h>
#include <cuda_bf16.h>
#include <math.h>
#include <stdint.h>

// Problem constants
#define BB    4
#define NN    4096
#define DD    256
#define MM    (BB * NN)        // 16384 flattened rows
#define MAXNZ 128

// ---------------------------------------------------------------------------
// Scratch (static __device__ — no allocations allowed)
// ---------------------------------------------------------------------------
static __device__ float          g_norm[MM];
static __device__ int            g_nnz[MM];
static __device__ int            g_cidx[MM * MAXNZ];
static __device__ float          g_cval[MM * MAXNZ];
static __device__ float          g_h[MM * DD];      // raw x@theta (no norm)
static __device__ float          g_het[MM * DD];    // x@W_h
static __device__ float          g_gate[MM * DD];   // sigmoid(x@W_t + b_t)
static __device__ __nv_bfloat16  g_xhi[MM * DD];
static __device__ __nv_bfloat16  g_xlo[MM * DD];
// W^T splits: [mat][hi/lo][n][k], each DD*DD
static __device__ __nv_bfloat16  g_wt[3 * 2 * DD * DD];

// ---------------------------------------------------------------------------
// PTX helpers (plain sm_100 target: mma.sync / ldmatrix / cp.async)
// ---------------------------------------------------------------------------
__device__ __forceinline__ uint32_t smem_u32(const void* p) {
    uint32_t a;
    asm("{ .reg .u64 t; cvta.to.shared.u64 t, %1; cvt.u32.u64 %0, t; }" : "=r"(a) : "l"(p));
    return a;
}
__device__ __forceinline__ void cp16(uint32_t dst, const void* src) {
    asm volatile("cp.async.cg.shared.global [%0], [%1], 16;" :: "r"(dst), "l"(src));
}
#define CP_COMMIT() asm volatile("cp.async.commit_group;" ::: "memory")
#define CP_WAIT(n)  asm volatile("cp.async.wait_group %0;" :: "n"(n) : "memory")

__device__ __forceinline__ void ldsm4(uint32_t* r, uint32_t a) {
    asm volatile("ldmatrix.sync.aligned.m8n8.x4.shared.b16 {%0,%1,%2,%3}, [%4];"
        : "=r"(r[0]), "=r"(r[1]), "=r"(r[2]), "=r"(r[3]) : "r"(a));
}
__device__ __forceinline__ void mma16816(float* d, const uint32_t* a, const uint32_t* b) {
    asm volatile(
        "mma.sync.aligned.m16n8k16.row.col.f32.bf16.bf16.f32 "
        "{%0,%1,%2,%3}, {%4,%5,%6,%7}, {%8,%9}, {%0,%1,%2,%3};"
        : "+f"(d[0]), "+f"(d[1]), "+f"(d[2]), "+f"(d[3])
        : "r"(a[0]), "r"(a[1]), "r"(a[2]), "r"(a[3]), "r"(b[0]), "r"(b[1]));
}

// SW128 swizzle for 128B rows: bank-rotate 16B chunks by row within 8-row group
__device__ __forceinline__ int swz128(int row, int intra) {
    return row * 128 + (intra ^ ((row & 7) * 16));
}

// ---------------------------------------------------------------------------
// K0: merged CSR + split-x + prep-w (all roles smem-free, regs-light,
// independent inputs/outputs). CSR blocks FIRST: the 256MB adj read is the
// long pole, so it starts at t=0 and the light roles overlap behind it.
//   blocks [0, 2048):        CSR extraction, one row per warp
//   blocks [2048, 6144):     split x into bf16 hi/lo
//   blocks [6144, 6912):     build W^T hi/lo
// ---------------------------------------------------------------------------
#define CSR_BLOCKS   2048
#define SPLIT_BLOCKS (MM * DD / 4 / 256)       // 4096
#define PREP_BLOCKS  (3 * DD * DD / 256)       // 768

__global__ __launch_bounds__(256) void k_front(const float* __restrict__ adj,
                                               const float* __restrict__ x,
                                               const float* __restrict__ theta,
                                               const float* __restrict__ Wh,
                                               const float* __restrict__ Wt) {
    const int bid = blockIdx.x;
    if (bid < CSR_BLOCKS) {
        // ---- CSR role: one adjacency row per warp, batched scan ----
        const int wid  = threadIdx.x >> 5;
        const int lane = threadIdx.x & 31;
        const int w    = bid * 8 + wid;
        const float4* rowp = (const float4*)(adj + (size_t)w * NN);
        const int base_out = w * MAXNZ;
        const int bbase    = w & ~(NN - 1);
        float degacc = 0.f;
        int   cnt    = 0;
        for (int it4 = 0; it4 < 4; ++it4) {
            float4 v[8];
            #pragma unroll
            for (int j = 0; j < 8; ++j)
                v[j] = rowp[it4 * 256 + j * 32 + lane];

            int lct = 0;
            #pragma unroll
            for (int j = 0; j < 8; ++j) {
                degacc += fabsf(v[j].x) + fabsf(v[j].y) + fabsf(v[j].z) + fabsf(v[j].w);
                lct += (v[j].x != 0.f) + (v[j].y != 0.f) + (v[j].z != 0.f) + (v[j].w != 0.f);
            }

            int scan = lct;
            #pragma unroll
            for (int o = 1; o < 32; o <<= 1) {
                int t = __shfl_up_sync(0xffffffffu, scan, o);
                if (lane >= o) scan += t;
            }
            int pos = cnt + (scan - lct);
            cnt += __shfl_sync(0xffffffffu, scan, 31);

            if (lct > 0) {
                #pragma unroll
                for (int j = 0; j < 8; ++j) {
                    int col = bbase + (it4 * 8 + j) * 128 + lane * 4;
                    if (v[j].x != 0.f && pos < MAXNZ) { g_cidx[base_out + pos] = col + 0; g_cval[base_out + pos] = v[j].x; pos++; }
                    if (v[j].y != 0.f && pos < MAXNZ) { g_cidx[base_out + pos] = col + 1; g_cval[base_out + pos] = v[j].y; pos++; }
                    if (v[j].z != 0.f && pos < MAXNZ) { g_cidx[base_out + pos] = col + 2; g_cval[base_out + pos] = v[j].z; pos++; }
                    if (v[j].w != 0.f && pos < MAXNZ) { g_cidx[base_out + pos] = col + 3; g_cval[base_out + pos] = v[j].w; pos++; }
                }
            }
        }
        #pragma unroll
        for (int o = 16; o; o >>= 1)
            degacc += __shfl_xor_sync(0xffffffffu, degacc, o);
        if (lane == 0) {
            g_nnz[w]  = cnt < MAXNZ ? cnt : MAXNZ;
            g_norm[w] = rsqrtf(degacc + 1e-6f);
        }
    } else if (bid < CSR_BLOCKS + SPLIT_BLOCKS) {
        // ---- split-x role ----
        int i = (bid - CSR_BLOCKS) * blockDim.x + threadIdx.x;   // over MM*DD/4
        float4 v = ((const float4*)x)[i];
        __nv_bfloat16 hx = __float2bfloat16(v.x), hy = __float2bfloat16(v.y);
        __nv_bfloat16 hz = __float2bfloat16(v.z), hw = __float2bfloat16(v.w);
        __nv_bfloat16 lx = __float2bfloat16(v.x - __bfloat162float(hx));
        __nv_bfloat16 ly = __float2bfloat16(v.y - __bfloat162float(hy));
        __nv_bfloat16 lz = __float2bfloat16(v.z - __bfloat162float(hz));
        __nv_bfloat16 lw = __float2bfloat16(v.w - __bfloat162float(hw));
        __nv_bfloat162* ph = (__nv_bfloat162*)&g_xhi[i * 4];
        __nv_bfloat162* pl = (__nv_bfloat162*)&g_xlo[i * 4];
        ph[0] = __nv_bfloat162(hx, hy); ph[1] = __nv_bfloat162(hz, hw);
        pl[0] = __nv_bfloat162(lx, ly); pl[1] = __nv_bfloat162(lz, lw);
    } else {
        // ---- prep-w role ----
        int i = (bid - CSR_BLOCKS - SPLIT_BLOCKS) * blockDim.x + threadIdx.x;  // over 3*DD*DD
        int mat = i >> 16;
        int r   = i & 65535;
        int n   = r >> 8;
        int k   = r & 255;
        const float* W = (mat == 0) ? theta : (mat == 1) ? Wh : Wt;
        float v = W[k * DD + n];
        __nv_bfloat16 hi = __float2bfloat16(v);
        __nv_bfloat16 lo = __float2bfloat16(v - __bfloat162float(hi));
        g_wt[((size_t)(mat * 2 + 0) << 16) + n * DD + k] = hi;
        g_wt[((size_t)(mat * 2 + 1) << 16) + n * DD + k] = lo;
    }
}

// ---------------------------------------------------------------------------
// K2: bf16-split GEMM via mma.sync.m16n8k16.
// CTA tile 128x128 (8 warps: 4m x 2n). BK=64, 3-stage cp.async ring (96KB
// dynamic smem), one __syncthreads per iteration.
// mats 0/1: 3-term split (12 iters); mat 2 (gate): single hi*hi pass (4).
// ---------------------------------------------------------------------------
#define TILE_B   (128 * 128)         // 16384 bytes per tile (A or B)
#define STAGE_B  (2 * TILE_B)        // 32768
#define GEMM_SMEM (3 * STAGE_B)      // 98304

__global__ __launch_bounds__(256, 2) void k_gemm_mma(const float* __restrict__ bt) {
    extern __shared__ __align__(128) char sm[];

    const int tid  = threadIdx.x;
    const int wid  = tid >> 5;
    const int lane = tid & 31;
    const int wm   = wid & 3;
    const int wn   = wid >> 2;
    const int g    = lane >> 3;
    const int lr   = lane & 7;

    const int mat   = blockIdx.y >> 1;
    const int nhalf = blockIdx.y & 1;
    const int m0    = blockIdx.x * 128;
    const int n0    = nhalf * 128;
    const __nv_bfloat16* wt_hi = g_wt + ((size_t)(mat * 2) << 16);
    const __nv_bfloat16* wt_lo = wt_hi + (1 << 16);

    const int niter = (mat == 2) ? 4 : 12;   // gate: single-pass bf16

    const uint32_t smb = smem_u32(sm);

    float acc[2][8][4] = {};

    auto load_stage = [&](int iter, int stage) {
        const int seg = iter >> 2;
        const int k0  = (iter & 3) * 64;
        const __nv_bfloat16* Asrc = (seg < 2) ? g_xhi : g_xlo;
        const __nv_bfloat16* Bsrc = (seg == 1) ? wt_lo : wt_hi;
        const uint32_t sa = smb + stage * STAGE_B;
        const uint32_t sb = sa + TILE_B;
        #pragma unroll
        for (int j = 0; j < 4; ++j) {
            int id  = tid + j * 256;
            int row = id >> 3, c = id & 7;
            int so  = swz128(row, c * 16);
            cp16(sa + so, Asrc + (size_t)(m0 + row) * DD + k0 + c * 8);
            cp16(sb + so, Bsrc + (size_t)(n0 + row) * DD + k0 + c * 8);
        }
        CP_COMMIT();
    };

    int aoff[2][4], boff[4][4];
    #pragma unroll
    for (int mi = 0; mi < 2; ++mi) {
        int r = wm * 32 + mi * 16 + (g & 1) * 8 + lr;
        #pragma unroll
        for (int ks = 0; ks < 4; ++ks)
            aoff[mi][ks] = swz128(r, ks * 32 + (g >> 1) * 16);
    }
    #pragma unroll
    for (int nt = 0; nt < 4; ++nt) {
        int r = wn * 64 + nt * 16 + (g >> 1) * 8 + lr;
        #pragma unroll
        for (int ks = 0; ks < 4; ++ks)
            boff[nt][ks] = swz128(r, ks * 32 + (g & 1) * 16);
    }

    load_stage(0, 0);
    load_stage(1, 1);

    int stage = 0;
    for (int it = 0; it < niter; ++it) {
        CP_WAIT(1);
        __syncthreads();

        if (it + 2 < niter) load_stage(it + 2, (stage + 2) % 3);

        const uint32_t sa = smb + stage * STAGE_B;
        const uint32_t sb = sa + TILE_B;

        #pragma unroll
        for (int ks = 0; ks < 4; ++ks) {
            uint32_t afrag[2][4], bfrag[4][4];
            #pragma unroll
            for (int mi = 0; mi < 2; ++mi)
                ldsm4(afrag[mi], sa + aoff[mi][ks]);
            #pragma unroll
            for (int nt = 0; nt < 4; ++nt)
                ldsm4(bfrag[nt], sb + boff[nt][ks]);
            #pragma unroll
            for (int mi = 0; mi < 2; ++mi)
                #pragma unroll
                for (int ni = 0; ni < 8; ++ni)
                    mma16816(acc[mi][ni], afrag[mi], &bfrag[ni >> 1][(ni & 1) * 2]);
        }
        stage = (stage + 1) % 3;
    }

    float* dst = (mat == 0) ? g_h : (mat == 1) ? g_het : g_gate;
    #pragma unroll
    for (int mi = 0; mi < 2; ++mi) {
        #pragma unroll
        for (int rh = 0; rh < 2; ++rh) {
            const int r = m0 + wm * 32 + mi * 16 + rh * 8 + (lane >> 2);
            #pragma unroll
            for (int ni = 0; ni < 8; ++ni) {
                const int c = n0 + wn * 64 + ni * 8 + (lane & 3) * 2;
                float v0 = acc[mi][ni][rh * 2];
                float v1 = acc[mi][ni][rh * 2 + 1];
                if (mat == 2) {
                    v0 = 1.f / (1.f + expf(-(v0 + bt[c])));
                    v1 = 1.f / (1.f + expf(-(v1 + bt[c + 1])));
                }
                *(float2*)(dst + (size_t)r * DD + c) = make_float2(v0, v1);
            }
        }
    }
}

// ---------------------------------------------------------------------------
// K3: vectorized sparse gather + gate/combine + ELU.
// 4 rows per block, 64 threads per row, float4 per thread. ~L2 roofline.
// ---------------------------------------------------------------------------
__global__ __launch_bounds__(256) void k_spmm(float* __restrict__ out) {
    const int grp = threadIdx.x >> 6;     // row within block (0..3)
    const int ch  = threadIdx.x & 63;     // channel group (x4)
    const int row = blockIdx.x * 4 + grp;

    __shared__ int   soff[4][MAXNZ];
    __shared__ float sval[4][MAXNZ];

    const int nnz = g_nnz[row];
    #pragma unroll
    for (int j = 0; j < 2; ++j) {
        int e = ch + j * 64;
        if (e < nnz) {
            int o = row * MAXNZ + e;
            int s = g_cidx[o];
            soff[grp][e] = s * DD;
            sval[grp][e] = g_cval[o] * g_norm[s];
        }
    }
    __syncthreads();

    const float* hbase = g_h + ch * 4;
    float4 acc = make_float4(0.f, 0.f, 0.f, 0.f);
    int e = 0;
    #pragma unroll 1
    for (; e + 4 <= nnz; e += 4) {
        float4 h0 = *(const float4*)(hbase + soff[grp][e]);
        float4 h1 = *(const float4*)(hbase + soff[grp][e + 1]);
        float4 h2 = *(const float4*)(hbase + soff[grp][e + 2]);
        float4 h3 = *(const float4*)(hbase + soff[grp][e + 3]);
        float v0 = sval[grp][e],     v1 = sval[grp][e + 1];
        float v2 = sval[grp][e + 2], v3 = sval[grp][e + 3];
        acc.x += v0 * h0.x; acc.y += v0 * h0.y; acc.z += v0 * h0.z; acc.w += v0 * h0.w;
        acc.x += v1 * h1.x; acc.y += v1 * h1.y; acc.z += v1 * h1.z; acc.w += v1 * h1.w;
        acc.x += v2 * h2.x; acc.y += v2 * h2.y; acc.z += v2 * h2.z; acc.w += v2 * h2.w;
        acc.x += v3 * h3.x; acc.y += v3 * h3.y; acc.z += v3 * h3.z; acc.w += v3 * h3.w;
    }
    for (; e < nnz; ++e) {
        float v = sval[grp][e];
        float4 hv = *(const float4*)(hbase + soff[grp][e]);
        acc.x += v * hv.x; acc.y += v * hv.y; acc.z += v * hv.z; acc.w += v * hv.w;
    }

    const size_t o = (size_t)row * DD + ch * 4;
    const float nrm = g_norm[row];
    float4 gt = *(const float4*)(g_gate + o);
    float4 ht = *(const float4*)(g_het + o);
    float4 f;
    f.x = gt.x * (acc.x * nrm) + (1.f - gt.x) * ht.x;
    f.y = gt.y * (acc.y * nrm) + (1.f - gt.y) * ht.y;
    f.z = gt.z * (acc.z * nrm) + (1.f - gt.z) * ht.z;
    f.w = gt.w * (acc.w * nrm) + (1.f - gt.w) * ht.w;
    f.x = f.x > 0.f ? f.x : expm1f(f.x);
    f.y = f.y > 0.f ? f.y : expm1f(f.y);
    f.z = f.z > 0.f ? f.z : expm1f(f.z);
    f.w = f.w > 0.f ? f.w : expm1f(f.w);
    *(float4*)(out + o) = f;
}

// ---------------------------------------------------------------------------
// Launch: single stream (fork-join rejected by platform — 2/2 container
// failures). Front kernel fuses CSR + split + prep (independent roles).
// ---------------------------------------------------------------------------
extern "C" void kernel_launch(void* const* d_in, const int* in_sizes, int n_in,
                              void* d_out, int out_size) {
    const float* x     = (const float*)d_in[0];
    const float* adj   = (const float*)d_in[1];
    const float* theta = (const float*)d_in[2];
    const float* Wh    = (const float*)d_in[3];
    const float* Wt    = (const float*)d_in[4];
    const float* bt    = (const float*)d_in[5];
    float* out = (float*)d_out;

    // Opt-in to >48KB dynamic smem (host-side attribute, immediate; capture-safe)
    cudaFuncSetAttribute(k_gemm_mma, cudaFuncAttributeMaxDynamicSharedMemorySize, GEMM_SMEM);

    k_front<<<CSR_BLOCKS + SPLIT_BLOCKS + PREP_BLOCKS, 256>>>(adj, x, theta, Wh, Wt);
    dim3 g2(MM / 128, 6);
    k_gemm_mma<<<g2, 256, GEMM_SMEM>>>(bt);
    k_spmm<<<MM / 4, 256>>>(out);
}